// round 13
// baseline (speedup 1.0000x reference)
#include <cuda_runtime.h>
#include <cuda_bf16.h>
#include <cstdint>

// ---------------- problem constants ----------------
#define B_   16
#define H_   224
#define W_   224
#define C_   96
#define TPX  112          // pixels owned per block
#define NT   256          // 8 warps
#define PW   52           // smem row pitch in 32-bit words (=104 bf16)

// ---------------- smem layout (uint32 words) ----------------
#define O_AHI 0                         // A hi: 128 x 52 words
#define O_ALO (128 * PW)                // A lo
#define O_WHI (2 * 128 * PW)            // W hi: 96 x 52 words
#define O_WLO (2 * 128 * PW + 96 * PW)  // W lo
#define O_KW  (2 * 128 * PW + 2 * 96 * PW)   // dw weights 9*96 f32 (nb-major)
#define O_SC  (O_KW + 9 * 96)
#define O_SH  (O_SC + 96)
#define O_DB  (O_SH + 96)
#define SMEM_WORDS (O_DB + 96)          // 24448
#define SMEM_BYTES (SMEM_WORDS * 4)     // 97792

// bf16 mma.sync m16n8k16 (legacy tensor path — compiles on compute_103 base)
__device__ __forceinline__ void mma16816(float* d,
    uint32_t a0, uint32_t a1, uint32_t a2, uint32_t a3,
    uint32_t b0, uint32_t b1)
{
    asm volatile(
        "mma.sync.aligned.m16n8k16.row.col.f32.bf16.bf16.f32 "
        "{%0,%1,%2,%3}, {%4,%5,%6,%7}, {%8,%9}, {%0,%1,%2,%3};"
        : "+f"(d[0]), "+f"(d[1]), "+f"(d[2]), "+f"(d[3])
        : "r"(a0), "r"(a1), "r"(a2), "r"(a3), "r"(b0), "r"(b1));
}

__device__ __forceinline__ uint32_t pack_bf2(float lo, float hi) {
    __nv_bfloat162 v = __floats2bfloat162_rn(lo, hi);   // .x = lo lane
    return *(uint32_t*)&v;
}

__device__ __forceinline__ void fma4(float4& a, const float4& xv, const float4& k) {
    a.x = fmaf(xv.x, k.x, a.x);
    a.y = fmaf(xv.y, k.y, a.y);
    a.z = fmaf(xv.z, k.z, a.z);
    a.w = fmaf(xv.w, k.w, a.w);
}

__global__ void __launch_bounds__(NT, 2)
sepconv_mma_kernel(const float* __restrict__ x,
                   const float* __restrict__ dwk,    // (3,3,1,96)
                   const float* __restrict__ dwb,    // (96)
                   const float* __restrict__ pwk,    // (1,1,96,96) [ci][co]
                   const float* __restrict__ pwb,    // (96)
                   const float* __restrict__ gamma,
                   const float* __restrict__ beta,
                   const float* __restrict__ mmean,
                   const float* __restrict__ mvar,
                   float* __restrict__ out)
{
    extern __shared__ uint32_t sm[];
    uint32_t* sAhi = sm + O_AHI;
    uint32_t* sAlo = sm + O_ALO;
    uint32_t* sWhi = sm + O_WHI;
    uint32_t* sWlo = sm + O_WLO;
    float* sKw = (float*)(sm + O_KW);
    float* sSc = (float*)(sm + O_SC);
    float* sSh = (float*)(sm + O_SH);
    float* sDb = (float*)(sm + O_DB);

    const int tid = threadIdx.x;
    const int wid = tid >> 5;
    const int l   = tid & 31;
    const int w0  = blockIdx.x * TPX;
    const int h   = blockIdx.y;
    const int b   = blockIdx.z;

    // ---- Phase 0: stage pointwise W (bf16 hi/lo, [co][ci]), dw weights, BN --
    for (int i = tid; i < C_ * (C_ / 2); i += NT) {
        int co = i / (C_ / 2);
        int cw = i - co * (C_ / 2);          // ci word (2 channels)
        float w0f = pwk[(2 * cw) * C_ + co];
        float w1f = pwk[(2 * cw + 1) * C_ + co];
        float h0 = __bfloat162float(__float2bfloat16_rn(w0f));
        float h1 = __bfloat162float(__float2bfloat16_rn(w1f));
        sWhi[co * PW + cw] = pack_bf2(h0, h1);
        sWlo[co * PW + cw] = pack_bf2(w0f - h0, w1f - h1);
    }
    for (int i = tid; i < 9 * C_; i += NT) sKw[i] = dwk[i];
    if (tid < C_) {
        float inv = gamma[tid] * rsqrtf(mvar[tid] + 1e-3f);
        sSc[tid] = inv;
        sSh[tid] = beta[tid] - mmean[tid] * inv + pwb[tid] * inv;
        sDb[tid] = dwb[tid];
    }
    __syncthreads();

    // ---- Phase A: depthwise, pixel-PAIR per item, row-outer kw hoist -------
    // Warp owns 16 pixels = 8 pairs; 8 pairs x 24 quads = 192 items = 6 its.
    // idx = it*32 + l: pair pp = idx/24, quad q = idx%24.
    // q has period 3 in it (32 mod 24 = 8): qs = it%3, q = (8*qs + l) % 24.
    {
        const float4* sKw4 = (const float4*)sKw;
        const float4* sDb4 = (const float4*)sDb;

        int qtab[3], ptab[6];
        #pragma unroll
        for (int qs = 0; qs < 3; qs++) qtab[qs] = (8 * qs + l) % 24;
        #pragma unroll
        for (int it = 0; it < 6; it++)
            ptab[it] = wid * 16 + ((it * 32 + l) / 24) * 2;   // pair base pixel

        float4 acc[6][2];
        #pragma unroll
        for (int it = 0; it < 6; it++) {
            float4 dbv = sDb4[qtab[it % 3]];
            acc[it][0] = dbv;
            acc[it][1] = dbv;
        }

        #pragma unroll
        for (int r = 0; r < 3; r++) {
            const int hh = h + r - 1;
            const bool hv = (unsigned)hh < (unsigned)H_;
            const float* xrow = x + ((size_t)b * H_ + hh) * (size_t)W_ * C_;

            float4 kwr[3][3];                 // [s][qs]
            #pragma unroll
            for (int s = 0; s < 3; s++)
                #pragma unroll
                for (int qs = 0; qs < 3; qs++)
                    kwr[s][qs] = sKw4[(r * 3 + s) * 24 + qtab[qs]];

            #pragma unroll
            for (int it = 0; it < 6; it++) {
                const int qs = it % 3;
                const int q  = qtab[qs];
                const int p0 = ptab[it];
                const int wwb = w0 + p0 - 1;          // col of xv[0]
                const float* cp = xrow + (size_t)wwb * C_ + q * 4;

                float4 xv[4];
                #pragma unroll
                for (int cc = 0; cc < 4; cc++) {
                    const bool v = hv && ((unsigned)(wwb + cc) < (unsigned)W_);
                    float4 t = v ? __ldg((const float4*)(cp + cc * C_))
                                 : make_float4(0.f, 0.f, 0.f, 0.f);
                    t.x = fmaxf(t.x, 0.f); t.y = fmaxf(t.y, 0.f);
                    t.z = fmaxf(t.z, 0.f); t.w = fmaxf(t.w, 0.f);
                    xv[cc] = t;
                }
                fma4(acc[it][0], xv[0], kwr[0][qs]);
                fma4(acc[it][0], xv[1], kwr[1][qs]);
                fma4(acc[it][0], xv[2], kwr[2][qs]);
                fma4(acc[it][1], xv[1], kwr[0][qs]);
                fma4(acc[it][1], xv[2], kwr[1][qs]);
                fma4(acc[it][1], xv[3], kwr[2][qs]);
            }
        }

        // split to bf16 hi/lo and store both pixels of each pair
        #pragma unroll
        for (int it = 0; it < 6; it++) {
            const int q  = qtab[it % 3];
            const int p0 = ptab[it];
            #pragma unroll
            for (int e = 0; e < 2; e++) {
                const float4 a = acc[it][e];
                float h0 = __bfloat162float(__float2bfloat16_rn(a.x));
                float h1 = __bfloat162float(__float2bfloat16_rn(a.y));
                float h2 = __bfloat162float(__float2bfloat16_rn(a.z));
                float h3 = __bfloat162float(__float2bfloat16_rn(a.w));
                const int wb = (p0 + e) * PW + q * 2;
                *(uint2*)(sAhi + wb) =
                    make_uint2(pack_bf2(h0, h1), pack_bf2(h2, h3));
                *(uint2*)(sAlo + wb) =
                    make_uint2(pack_bf2(a.x - h0, a.y - h1),
                               pack_bf2(a.z - h2, a.w - h3));
            }
        }
    }
    __syncthreads();

    // ---- Phase B: GEMM M=128 N=96 K=96, bf16 split (hi*hi + hi*lo + lo*hi) --
    const int m0 = wid * 16;
    const int g  = l >> 2;
    const int tg = l & 3;

    float d[12][4];
    #pragma unroll
    for (int j = 0; j < 12; j++) {
        d[j][0] = 0.f; d[j][1] = 0.f; d[j][2] = 0.f; d[j][3] = 0.f;
    }

    #pragma unroll
    for (int k = 0; k < 6; k++) {          // k0 = k*16, word base k*8
        const int aw = (m0 + g) * PW + k * 8 + tg;
        const uint32_t ah0 = sAhi[aw];
        const uint32_t ah1 = sAhi[aw + 8 * PW];
        const uint32_t ah2 = sAhi[aw + 4];
        const uint32_t ah3 = sAhi[aw + 8 * PW + 4];
        const uint32_t al0 = sAlo[aw];
        const uint32_t al1 = sAlo[aw + 8 * PW];
        const uint32_t al2 = sAlo[aw + 4];
        const uint32_t al3 = sAlo[aw + 8 * PW + 4];
        #pragma unroll
        for (int j = 0; j < 12; j++) {
            const int bw = (j * 8 + g) * PW + k * 8 + tg;
            const uint32_t bh0 = sWhi[bw];
            const uint32_t bh1 = sWhi[bw + 4];
            const uint32_t bl0 = sWlo[bw];
            const uint32_t bl1 = sWlo[bw + 4];
            mma16816(d[j], ah0, ah1, ah2, ah3, bh0, bh1);
            mma16816(d[j], ah0, ah1, ah2, ah3, bl0, bl1);
            mma16816(d[j], al0, al1, al2, al3, bh0, bh1);
        }
    }

    // ---- Epilogue: BN + store (rows 0..111 only -> warps 0..6) -------------
    if (wid < 7) {
        const int r0 = m0 + g;
        float* base0 = out + (((size_t)b * H_ + h) * W_ + (w0 + r0)) * C_;
        float* base1 = base0 + 8 * (size_t)C_;
        #pragma unroll
        for (int j = 0; j < 12; j++) {
            const int col = j * 8 + tg * 2;
            float2 sc = *(const float2*)(sSc + col);
            float2 sh = *(const float2*)(sSh + col);
            float2 r;
            r.x = fmaf(d[j][0], sc.x, sh.x);
            r.y = fmaf(d[j][1], sc.y, sh.y);
            *(float2*)(base0 + col) = r;
            r.x = fmaf(d[j][2], sc.x, sh.x);
            r.y = fmaf(d[j][3], sc.y, sh.y);
            *(float2*)(base1 + col) = r;
        }
    }
}

extern "C" void kernel_launch(void* const* d_in, const int* in_sizes, int n_in,
                              void* d_out, int out_size)
{
    (void)in_sizes; (void)n_in; (void)out_size;
    const float* x     = (const float*)d_in[0];
    const float* dwk   = (const float*)d_in[1];
    const float* dwb   = (const float*)d_in[2];
    const float* pwk   = (const float*)d_in[3];
    const float* pwb   = (const float*)d_in[4];
    const float* gamma = (const float*)d_in[5];
    const float* beta  = (const float*)d_in[6];
    const float* mmean = (const float*)d_in[7];
    const float* mvar  = (const float*)d_in[8];
    float* out = (float*)d_out;

    cudaFuncSetAttribute(sepconv_mma_kernel,
                         cudaFuncAttributeMaxDynamicSharedMemorySize, SMEM_BYTES);

    dim3 grid(W_ / TPX, H_, B_);           // (2, 224, 16)
    sepconv_mma_kernel<<<grid, NT, SMEM_BYTES>>>(
        x, dwk, dwb, pwk, pwb, gamma, beta, mmean, mvar, out);
}

// round 14
// speedup vs baseline: 1.5726x; 1.5726x over previous
#include <cuda_runtime.h>
#include <cuda_bf16.h>
#include <cstdint>

// ---------------- problem constants ----------------
#define B_   16
#define H_   224
#define W_   224
#define C_   96
#define TPX  112          // pixels owned per block
#define NT   256          // 8 warps
#define PW   52           // smem row pitch in 32-bit words (=104 bf16)

// ---------------- smem layout (uint32 words) ----------------
#define O_AHI 0                         // A hi: 128 x 52 words
#define O_ALO (128 * PW)                // A lo
#define O_WHI (2 * 128 * PW)            // W hi: 96 x 52 words
#define O_WLO (2 * 128 * PW + 96 * PW)  // W lo
#define O_KW  (2 * 128 * PW + 2 * 96 * PW)   // dw weights 9*96 f32 (nb-major)
#define O_SC  (O_KW + 9 * 96)
#define O_SH  (O_SC + 96)
#define O_DB  (O_SH + 96)
#define SMEM_WORDS (O_DB + 96)          // 24448
#define SMEM_BYTES (SMEM_WORDS * 4)     // 97792

// bf16 mma.sync m16n8k16 (legacy tensor path — compiles on compute_103 base)
__device__ __forceinline__ void mma16816(float* d,
    uint32_t a0, uint32_t a1, uint32_t a2, uint32_t a3,
    uint32_t b0, uint32_t b1)
{
    asm volatile(
        "mma.sync.aligned.m16n8k16.row.col.f32.bf16.bf16.f32 "
        "{%0,%1,%2,%3}, {%4,%5,%6,%7}, {%8,%9}, {%0,%1,%2,%3};"
        : "+f"(d[0]), "+f"(d[1]), "+f"(d[2]), "+f"(d[3])
        : "r"(a0), "r"(a1), "r"(a2), "r"(a3), "r"(b0), "r"(b1));
}

__device__ __forceinline__ uint32_t pack_bf2(float lo, float hi) {
    __nv_bfloat162 v = __floats2bfloat162_rn(lo, hi);   // .x = lo lane
    return *(uint32_t*)&v;
}

__device__ __forceinline__ void fma4(float4& a, const float4& xv, const float4& k) {
    a.x = fmaf(xv.x, k.x, a.x);
    a.y = fmaf(xv.y, k.y, a.y);
    a.z = fmaf(xv.z, k.z, a.z);
    a.w = fmaf(xv.w, k.w, a.w);
}

__global__ void __launch_bounds__(NT, 2)
sepconv_mma_kernel(const float* __restrict__ x,
                   const float* __restrict__ dwk,    // (3,3,1,96)
                   const float* __restrict__ dwb,    // (96)
                   const float* __restrict__ pwk,    // (1,1,96,96) [ci][co]
                   const float* __restrict__ pwb,    // (96)
                   const float* __restrict__ gamma,
                   const float* __restrict__ beta,
                   const float* __restrict__ mmean,
                   const float* __restrict__ mvar,
                   float* __restrict__ out)
{
    extern __shared__ uint32_t sm[];
    uint32_t* sAhi = sm + O_AHI;
    uint32_t* sAlo = sm + O_ALO;
    uint32_t* sWhi = sm + O_WHI;
    uint32_t* sWlo = sm + O_WLO;
    float* sKw = (float*)(sm + O_KW);
    float* sSc = (float*)(sm + O_SC);
    float* sSh = (float*)(sm + O_SH);
    float* sDb = (float*)(sm + O_DB);

    const int tid = threadIdx.x;
    const int wid = tid >> 5;
    const int l   = tid & 31;
    const int w0  = blockIdx.x * TPX;
    const int h   = blockIdx.y;
    const int b   = blockIdx.z;

    // ---- Phase 0: stage pointwise W (bf16 hi/lo, [co][ci]), dw weights, BN --
    for (int i = tid; i < C_ * (C_ / 2); i += NT) {
        int co = i / (C_ / 2);
        int cw = i - co * (C_ / 2);          // ci word (2 channels)
        float w0f = pwk[(2 * cw) * C_ + co];
        float w1f = pwk[(2 * cw + 1) * C_ + co];
        float h0 = __bfloat162float(__float2bfloat16_rn(w0f));
        float h1 = __bfloat162float(__float2bfloat16_rn(w1f));
        sWhi[co * PW + cw] = pack_bf2(h0, h1);
        sWlo[co * PW + cw] = pack_bf2(w0f - h0, w1f - h1);
    }
    for (int i = tid; i < 9 * C_; i += NT) sKw[i] = dwk[i];
    if (tid < C_) {
        float inv = gamma[tid] * rsqrtf(mvar[tid] + 1e-3f);
        sSc[tid] = inv;
        sSh[tid] = beta[tid] - mmean[tid] * inv + pwb[tid] * inv;
        sDb[tid] = dwb[tid];
    }
    __syncthreads();

    // ---- Phase A: depthwise, 4 pixels x 1 quad per item, item-at-a-time ----
    // Warp owns 16 pixels; items = 4 pixel-groups x 24 quads = 96 = 3 its x 32.
    // item = it*32 + l: q = item % 24, grp = item / 24.
    // Per item: 3 rows x 6 horizontal loads feed 12 taps (redundancy 1.5 vs 3).
    {
        const float4* sKw4 = (const float4*)sKw;
        const float4* sDb4 = (const float4*)sDb;
        const int base = wid * 16;

        #pragma unroll
        for (int it = 0; it < 3; it++) {
            const int item = it * 32 + l;
            const int q    = item % 24;            // channel quad
            const int grp  = item / 24;            // pixel group (0..3)
            const int p0   = base + grp * 4;       // first of 4 pixels
            const int wwb  = w0 + p0 - 1;          // col of xv[0]

            const float4 dbv = sDb4[q];
            float4 acc0 = dbv, acc1 = dbv, acc2 = dbv, acc3 = dbv;

            #pragma unroll
            for (int r = 0; r < 3; r++) {
                const int hh = h + r - 1;
                const bool hv = (unsigned)hh < (unsigned)H_;
                const float* xrow = x + ((size_t)b * H_ + hh) * (size_t)W_ * C_;

                const float4 k0 = sKw4[(r * 3 + 0) * 24 + q];
                const float4 k1 = sKw4[(r * 3 + 1) * 24 + q];
                const float4 k2 = sKw4[(r * 3 + 2) * 24 + q];

                float4 xv[6];
                #pragma unroll
                for (int cc = 0; cc < 6; cc++) {
                    const int ww = wwb + cc;
                    const bool v = hv && ((unsigned)ww < (unsigned)W_);
                    float4 t = v ? __ldg((const float4*)(xrow + (size_t)ww * C_) + q)
                                 : make_float4(0.f, 0.f, 0.f, 0.f);
                    t.x = fmaxf(t.x, 0.f); t.y = fmaxf(t.y, 0.f);
                    t.z = fmaxf(t.z, 0.f); t.w = fmaxf(t.w, 0.f);
                    xv[cc] = t;
                }
                fma4(acc0, xv[0], k0); fma4(acc0, xv[1], k1); fma4(acc0, xv[2], k2);
                fma4(acc1, xv[1], k0); fma4(acc1, xv[2], k1); fma4(acc1, xv[3], k2);
                fma4(acc2, xv[2], k0); fma4(acc2, xv[3], k1); fma4(acc2, xv[4], k2);
                fma4(acc3, xv[3], k0); fma4(acc3, xv[4], k1); fma4(acc3, xv[5], k2);
            }

            // split to bf16 hi/lo and store the 4 pixels of this item
            float4 av[4] = {acc0, acc1, acc2, acc3};
            #pragma unroll
            for (int e = 0; e < 4; e++) {
                const float4 a = av[e];
                float h0 = __bfloat162float(__float2bfloat16_rn(a.x));
                float h1 = __bfloat162float(__float2bfloat16_rn(a.y));
                float h2 = __bfloat162float(__float2bfloat16_rn(a.z));
                float h3 = __bfloat162float(__float2bfloat16_rn(a.w));
                const int wb = (p0 + e) * PW + q * 2;
                *(uint2*)(sAhi + wb) =
                    make_uint2(pack_bf2(h0, h1), pack_bf2(h2, h3));
                *(uint2*)(sAlo + wb) =
                    make_uint2(pack_bf2(a.x - h0, a.y - h1),
                               pack_bf2(a.z - h2, a.w - h3));
            }
        }
    }
    __syncthreads();

    // ---- Phase B: GEMM M=128 N=96 K=96, bf16 split (hi*hi + hi*lo + lo*hi) --
    const int m0 = wid * 16;
    const int g  = l >> 2;
    const int tg = l & 3;

    float d[12][4];
    #pragma unroll
    for (int j = 0; j < 12; j++) {
        d[j][0] = 0.f; d[j][1] = 0.f; d[j][2] = 0.f; d[j][3] = 0.f;
    }

    #pragma unroll
    for (int k = 0; k < 6; k++) {          // k0 = k*16, word base k*8
        const int aw = (m0 + g) * PW + k * 8 + tg;
        const uint32_t ah0 = sAhi[aw];
        const uint32_t ah1 = sAhi[aw + 8 * PW];
        const uint32_t ah2 = sAhi[aw + 4];
        const uint32_t ah3 = sAhi[aw + 8 * PW + 4];
        const uint32_t al0 = sAlo[aw];
        const uint32_t al1 = sAlo[aw + 8 * PW];
        const uint32_t al2 = sAlo[aw + 4];
        const uint32_t al3 = sAlo[aw + 8 * PW + 4];
        #pragma unroll
        for (int j = 0; j < 12; j++) {
            const int bw = (j * 8 + g) * PW + k * 8 + tg;
            const uint32_t bh0 = sWhi[bw];
            const uint32_t bh1 = sWhi[bw + 4];
            const uint32_t bl0 = sWlo[bw];
            const uint32_t bl1 = sWlo[bw + 4];
            mma16816(d[j], ah0, ah1, ah2, ah3, bh0, bh1);
            mma16816(d[j], ah0, ah1, ah2, ah3, bl0, bl1);
            mma16816(d[j], al0, al1, al2, al3, bh0, bh1);
        }
    }

    // ---- Epilogue: BN + store (rows 0..111 only -> warps 0..6) -------------
    if (wid < 7) {
        const int r0 = m0 + g;
        float* base0 = out + (((size_t)b * H_ + h) * W_ + (w0 + r0)) * C_;
        float* base1 = base0 + 8 * (size_t)C_;
        #pragma unroll
        for (int j = 0; j < 12; j++) {
            const int col = j * 8 + tg * 2;
            float2 sc = *(const float2*)(sSc + col);
            float2 sh = *(const float2*)(sSh + col);
            float2 r;
            r.x = fmaf(d[j][0], sc.x, sh.x);
            r.y = fmaf(d[j][1], sc.y, sh.y);
            *(float2*)(base0 + col) = r;
            r.x = fmaf(d[j][2], sc.x, sh.x);
            r.y = fmaf(d[j][3], sc.y, sh.y);
            *(float2*)(base1 + col) = r;
        }
    }
}

extern "C" void kernel_launch(void* const* d_in, const int* in_sizes, int n_in,
                              void* d_out, int out_size)
{
    (void)in_sizes; (void)n_in; (void)out_size;
    const float* x     = (const float*)d_in[0];
    const float* dwk   = (const float*)d_in[1];
    const float* dwb   = (const float*)d_in[2];
    const float* pwk   = (const float*)d_in[3];
    const float* pwb   = (const float*)d_in[4];
    const float* gamma = (const float*)d_in[5];
    const float* beta  = (const float*)d_in[6];
    const float* mmean = (const float*)d_in[7];
    const float* mvar  = (const float*)d_in[8];
    float* out = (float*)d_out;

    cudaFuncSetAttribute(sepconv_mma_kernel,
                         cudaFuncAttributeMaxDynamicSharedMemorySize, SMEM_BYTES);

    dim3 grid(W_ / TPX, H_, B_);           // (2, 224, 16)
    sepconv_mma_kernel<<<grid, NT, SMEM_BYTES>>>(
        x, dwk, dwb, pwk, pwb, gamma, beta, mmean, mvar, out);
}

// round 15
// speedup vs baseline: 1.5819x; 1.0059x over previous
#include <cuda_runtime.h>
#include <cuda_bf16.h>
#include <cstdint>

// ---------------- problem constants ----------------
#define B_   16
#define H_   224
#define W_   224
#define C_   96
#define TPX  112          // pixels owned per block
#define NT   256          // 8 warps
#define PW   52           // smem row pitch in 32-bit words (=104 bf16)

// ---------------- smem layout (uint32 words) ----------------
#define O_AHI 0                         // A hi: 128 x 52 words
#define O_ALO (128 * PW)                // A lo
#define O_WHI (2 * 128 * PW)            // W hi: 96 x 52 words
#define O_WLO (2 * 128 * PW + 96 * PW)  // W lo
#define O_KW  (2 * 128 * PW + 2 * 96 * PW)   // dw weights 9*96 f32 (nb-major)
#define O_SC  (O_KW + 9 * 96)
#define O_SH  (O_SC + 96)
#define O_DB  (O_SH + 96)
#define SMEM_WORDS (O_DB + 96)          // 24448
#define SMEM_BYTES (SMEM_WORDS * 4)     // 97792

// bf16 mma.sync m16n8k16 (legacy tensor path — compiles on compute_103 base)
__device__ __forceinline__ void mma16816(float* d,
    uint32_t a0, uint32_t a1, uint32_t a2, uint32_t a3,
    uint32_t b0, uint32_t b1)
{
    asm volatile(
        "mma.sync.aligned.m16n8k16.row.col.f32.bf16.bf16.f32 "
        "{%0,%1,%2,%3}, {%4,%5,%6,%7}, {%8,%9}, {%0,%1,%2,%3};"
        : "+f"(d[0]), "+f"(d[1]), "+f"(d[2]), "+f"(d[3])
        : "r"(a0), "r"(a1), "r"(a2), "r"(a3), "r"(b0), "r"(b1));
}

// ldmatrix 4x m8n8 b16 fragments (sm_75+ PTX, fine on compute_103 base)
__device__ __forceinline__ void ldsm_x4(uint32_t* r, uint32_t addr) {
    asm volatile(
        "ldmatrix.sync.aligned.m8n8.x4.shared.b16 {%0,%1,%2,%3}, [%4];"
        : "=r"(r[0]), "=r"(r[1]), "=r"(r[2]), "=r"(r[3]) : "r"(addr));
}

__device__ __forceinline__ uint32_t smem_u32(const void* p) {
    uint32_t a;
    asm("{ .reg .u64 t; cvta.to.shared.u64 t, %1; cvt.u32.u64 %0, t; }"
        : "=r"(a) : "l"(p));
    return a;
}

__device__ __forceinline__ uint32_t pack_bf2(float lo, float hi) {
    __nv_bfloat162 v = __floats2bfloat162_rn(lo, hi);   // .x = lo lane
    return *(uint32_t*)&v;
}

__device__ __forceinline__ void fma4(float4& a, const float4& xv, const float4& k) {
    a.x = fmaf(xv.x, k.x, a.x);
    a.y = fmaf(xv.y, k.y, a.y);
    a.z = fmaf(xv.z, k.z, a.z);
    a.w = fmaf(xv.w, k.w, a.w);
}

__global__ void __launch_bounds__(NT, 2)
sepconv_mma_kernel(const float* __restrict__ x,
                   const float* __restrict__ dwk,    // (3,3,1,96)
                   const float* __restrict__ dwb,    // (96)
                   const float* __restrict__ pwk,    // (1,1,96,96) [ci][co]
                   const float* __restrict__ pwb,    // (96)
                   const float* __restrict__ gamma,
                   const float* __restrict__ beta,
                   const float* __restrict__ mmean,
                   const float* __restrict__ mvar,
                   float* __restrict__ out)
{
    extern __shared__ uint32_t sm[];
    uint32_t* sAhi = sm + O_AHI;
    uint32_t* sAlo = sm + O_ALO;
    uint32_t* sWhi = sm + O_WHI;
    uint32_t* sWlo = sm + O_WLO;
    float* sKw = (float*)(sm + O_KW);
    float* sSc = (float*)(sm + O_SC);
    float* sSh = (float*)(sm + O_SH);
    float* sDb = (float*)(sm + O_DB);

    const int tid = threadIdx.x;
    const int wid = tid >> 5;
    const int l   = tid & 31;
    const int w0  = blockIdx.x * TPX;
    const int h   = blockIdx.y;
    const int b   = blockIdx.z;

    // ---- Phase 0: stage pointwise W (bf16 hi/lo, [co][ci]), dw weights, BN --
    for (int i = tid; i < C_ * (C_ / 2); i += NT) {
        int co = i / (C_ / 2);
        int cw = i - co * (C_ / 2);          // ci word (2 channels)
        float w0f = pwk[(2 * cw) * C_ + co];
        float w1f = pwk[(2 * cw + 1) * C_ + co];
        float h0 = __bfloat162float(__float2bfloat16_rn(w0f));
        float h1 = __bfloat162float(__float2bfloat16_rn(w1f));
        sWhi[co * PW + cw] = pack_bf2(h0, h1);
        sWlo[co * PW + cw] = pack_bf2(w0f - h0, w1f - h1);
    }
    for (int i = tid; i < 9 * C_; i += NT) sKw[i] = dwk[i];
    if (tid < C_) {
        float inv = gamma[tid] * rsqrtf(mvar[tid] + 1e-3f);
        sSc[tid] = inv;
        sSh[tid] = beta[tid] - mmean[tid] * inv + pwb[tid] * inv;
        sDb[tid] = dwb[tid];
    }
    __syncthreads();

    // ---- Phase A: depthwise, 4 pixels x 1 quad per item, item-at-a-time ----
    {
        const float4* sKw4 = (const float4*)sKw;
        const float4* sDb4 = (const float4*)sDb;
        const int base = wid * 16;

        #pragma unroll
        for (int it = 0; it < 3; it++) {
            const int item = it * 32 + l;
            const int q    = item % 24;            // channel quad
            const int grp  = item / 24;            // pixel group (0..3)
            const int p0   = base + grp * 4;       // first of 4 pixels
            const int wwb  = w0 + p0 - 1;          // col of xv[0]

            const float4 dbv = sDb4[q];
            float4 acc0 = dbv, acc1 = dbv, acc2 = dbv, acc3 = dbv;

            #pragma unroll
            for (int r = 0; r < 3; r++) {
                const int hh = h + r - 1;
                const bool hv = (unsigned)hh < (unsigned)H_;
                const float* xrow = x + ((size_t)b * H_ + hh) * (size_t)W_ * C_;

                const float4 k0 = sKw4[(r * 3 + 0) * 24 + q];
                const float4 k1 = sKw4[(r * 3 + 1) * 24 + q];
                const float4 k2 = sKw4[(r * 3 + 2) * 24 + q];

                float4 xv[6];
                #pragma unroll
                for (int cc = 0; cc < 6; cc++) {
                    const int ww = wwb + cc;
                    const bool v = hv && ((unsigned)ww < (unsigned)W_);
                    float4 t = v ? __ldg((const float4*)(xrow + (size_t)ww * C_) + q)
                                 : make_float4(0.f, 0.f, 0.f, 0.f);
                    t.x = fmaxf(t.x, 0.f); t.y = fmaxf(t.y, 0.f);
                    t.z = fmaxf(t.z, 0.f); t.w = fmaxf(t.w, 0.f);
                    xv[cc] = t;
                }
                fma4(acc0, xv[0], k0); fma4(acc0, xv[1], k1); fma4(acc0, xv[2], k2);
                fma4(acc1, xv[1], k0); fma4(acc1, xv[2], k1); fma4(acc1, xv[3], k2);
                fma4(acc2, xv[2], k0); fma4(acc2, xv[3], k1); fma4(acc2, xv[4], k2);
                fma4(acc3, xv[3], k0); fma4(acc3, xv[4], k1); fma4(acc3, xv[5], k2);
            }

            // split to bf16 hi/lo and store the 4 pixels of this item
            float4 av[4] = {acc0, acc1, acc2, acc3};
            #pragma unroll
            for (int e = 0; e < 4; e++) {
                const float4 a = av[e];
                float h0 = __bfloat162float(__float2bfloat16_rn(a.x));
                float h1 = __bfloat162float(__float2bfloat16_rn(a.y));
                float h2 = __bfloat162float(__float2bfloat16_rn(a.z));
                float h3 = __bfloat162float(__float2bfloat16_rn(a.w));
                const int wb = (p0 + e) * PW + q * 2;
                *(uint2*)(sAhi + wb) =
                    make_uint2(pack_bf2(h0, h1), pack_bf2(h2, h3));
                *(uint2*)(sAlo + wb) =
                    make_uint2(pack_bf2(a.x - h0, a.y - h1),
                               pack_bf2(a.z - h2, a.w - h3));
            }
        }
    }
    __syncthreads();

    // ---- Phase B: GEMM M=128 N=96 K=96 via ldmatrix fragments --------------
    // A x4: matrices = [(m0-7,k0-7),(m8-15,k0-7),(m0-7,k8-15),(m8-15,k8-15)]
    // B x4 per j-pair: [(j0,k0-7),(j0,k8-15),(j1,k0-7),(j1,k8-15)]
    const int m0 = wid * 16;
    const int g  = l >> 2;
    const int tg = l & 3;

    const uint32_t sbase = smem_u32(sm);
    const int arow = m0 + ((l >> 3) & 1) * 8 + (l & 7);
    const int acol = (l >> 4) * 4;                 // word offset within k-chunk
    const int brow = ((l >> 4) * 8) + (l & 7);     // + jp*16 at use site
    const int bcol = ((l >> 3) & 1) * 4;

    const uint32_t a_hi = sbase + (uint32_t)(O_AHI + arow * PW + acol) * 4u;
    const uint32_t a_lo = sbase + (uint32_t)(O_ALO + arow * PW + acol) * 4u;
    const uint32_t b_hi = sbase + (uint32_t)(O_WHI + brow * PW + bcol) * 4u;
    const uint32_t b_lo = sbase + (uint32_t)(O_WLO + brow * PW + bcol) * 4u;

    float d[12][4];
    #pragma unroll
    for (int j = 0; j < 12; j++) {
        d[j][0] = 0.f; d[j][1] = 0.f; d[j][2] = 0.f; d[j][3] = 0.f;
    }

    #pragma unroll
    for (int k = 0; k < 6; k++) {                  // byte step: 8 words = 32B
        uint32_t ah[4], al[4];
        ldsm_x4(ah, a_hi + k * 32u);
        ldsm_x4(al, a_lo + k * 32u);
        #pragma unroll
        for (int jp = 0; jp < 6; jp++) {
            uint32_t bh[4], bl[4];
            const uint32_t joff = (uint32_t)jp * (16u * PW * 4u) + k * 32u;
            ldsm_x4(bh, b_hi + joff);
            ldsm_x4(bl, b_lo + joff);
            float* d0 = d[2 * jp];
            float* d1 = d[2 * jp + 1];
            mma16816(d0, ah[0], ah[1], ah[2], ah[3], bh[0], bh[1]);
            mma16816(d0, ah[0], ah[1], ah[2], ah[3], bl[0], bl[1]);
            mma16816(d0, al[0], al[1], al[2], al[3], bh[0], bh[1]);
            mma16816(d1, ah[0], ah[1], ah[2], ah[3], bh[2], bh[3]);
            mma16816(d1, ah[0], ah[1], ah[2], ah[3], bl[2], bl[3]);
            mma16816(d1, al[0], al[1], al[2], al[3], bh[2], bh[3]);
        }
    }

    // ---- Epilogue: BN + store (rows 0..111 only -> warps 0..6) -------------
    if (wid < 7) {
        const int r0 = m0 + g;
        float* base0 = out + (((size_t)b * H_ + h) * W_ + (w0 + r0)) * C_;
        float* base1 = base0 + 8 * (size_t)C_;
        #pragma unroll
        for (int j = 0; j < 12; j++) {
            const int col = j * 8 + tg * 2;
            float2 sc = *(const float2*)(sSc + col);
            float2 sh = *(const float2*)(sSh + col);
            float2 r;
            r.x = fmaf(d[j][0], sc.x, sh.x);
            r.y = fmaf(d[j][1], sc.y, sh.y);
            *(float2*)(base0 + col) = r;
            r.x = fmaf(d[j][2], sc.x, sh.x);
            r.y = fmaf(d[j][3], sc.y, sh.y);
            *(float2*)(base1 + col) = r;
        }
    }
}

extern "C" void kernel_launch(void* const* d_in, const int* in_sizes, int n_in,
                              void* d_out, int out_size)
{
    (void)in_sizes; (void)n_in; (void)out_size;
    const float* x     = (const float*)d_in[0];
    const float* dwk   = (const float*)d_in[1];
    const float* dwb   = (const float*)d_in[2];
    const float* pwk   = (const float*)d_in[3];
    const float* pwb   = (const float*)d_in[4];
    const float* gamma = (const float*)d_in[5];
    const float* beta  = (const float*)d_in[6];
    const float* mmean = (const float*)d_in[7];
    const float* mvar  = (const float*)d_in[8];
    float* out = (float*)d_out;

    cudaFuncSetAttribute(sepconv_mma_kernel,
                         cudaFuncAttributeMaxDynamicSharedMemorySize, SMEM_BYTES);

    dim3 grid(W_ / TPX, H_, B_);           // (2, 224, 16)
    sepconv_mma_kernel<<<grid, NT, SMEM_BYTES>>>(
        x, dwk, dwb, pwk, pwb, gamma, beta, mmean, mvar, out);
}

// round 16
// speedup vs baseline: 1.9109x; 1.2080x over previous
#include <cuda_runtime.h>
#include <cuda_bf16.h>
#include <cstdint>

// ---------------- problem constants ----------------
#define B_   16
#define H_   224
#define W_   224
#define C_   96
#define TPX  112          // valid pixels per block (per output row)
#define NT   384          // 12 warps
#define PW   52           // smem row pitch in 32-bit words (=104 bf16)

// ---------------- smem layout (uint32 words) ----------------
// A: 256 rows (row p = out-row h2 pixel p; row 128+p = out-row h2+1)
#define O_AHI 0                          // 256*52 = 13312
#define O_ALO 13312
#define O_WHI 26624                      // W hi: 96 x 52
#define O_WLO 31616
#define O_KW  36608                      // dw weights 9*96 f32
#define O_SC  (O_KW + 9 * 96)
#define O_SH  (O_SC + 96)
#define O_DB  (O_SH + 96)
#define SMEM_WORDS (O_DB + 96)           // 37760
#define SMEM_BYTES (SMEM_WORDS * 4)      // 151040

__device__ __forceinline__ void mma16816(float* d,
    uint32_t a0, uint32_t a1, uint32_t a2, uint32_t a3,
    uint32_t b0, uint32_t b1)
{
    asm volatile(
        "mma.sync.aligned.m16n8k16.row.col.f32.bf16.bf16.f32 "
        "{%0,%1,%2,%3}, {%4,%5,%6,%7}, {%8,%9}, {%0,%1,%2,%3};"
        : "+f"(d[0]), "+f"(d[1]), "+f"(d[2]), "+f"(d[3])
        : "r"(a0), "r"(a1), "r"(a2), "r"(a3), "r"(b0), "r"(b1));
}

__device__ __forceinline__ void ldsm_x4(uint32_t* r, uint32_t addr) {
    asm volatile(
        "ldmatrix.sync.aligned.m8n8.x4.shared.b16 {%0,%1,%2,%3}, [%4];"
        : "=r"(r[0]), "=r"(r[1]), "=r"(r[2]), "=r"(r[3]) : "r"(addr));
}

__device__ __forceinline__ uint32_t smem_u32(const void* p) {
    uint32_t a;
    asm("{ .reg .u64 t; cvta.to.shared.u64 t, %1; cvt.u32.u64 %0, t; }"
        : "=r"(a) : "l"(p));
    return a;
}

__device__ __forceinline__ uint32_t pack_bf2(float lo, float hi) {
    __nv_bfloat162 v = __floats2bfloat162_rn(lo, hi);   // .x = lo lane
    return *(uint32_t*)&v;
}

__device__ __forceinline__ void fma4(float4& a, const float4& xv, const float4& k) {
    a.x = fmaf(xv.x, k.x, a.x);
    a.y = fmaf(xv.y, k.y, a.y);
    a.z = fmaf(xv.z, k.z, a.z);
    a.w = fmaf(xv.w, k.w, a.w);
}

__device__ __forceinline__ void store_split(uint32_t* sAhi, uint32_t* sAlo,
                                            int row, int q, float4 a)
{
    float h0 = __bfloat162float(__float2bfloat16_rn(a.x));
    float h1 = __bfloat162float(__float2bfloat16_rn(a.y));
    float h2 = __bfloat162float(__float2bfloat16_rn(a.z));
    float h3 = __bfloat162float(__float2bfloat16_rn(a.w));
    const int wb = row * PW + q * 2;
    *(uint2*)(sAhi + wb) = make_uint2(pack_bf2(h0, h1), pack_bf2(h2, h3));
    *(uint2*)(sAlo + wb) = make_uint2(pack_bf2(a.x - h0, a.y - h1),
                                      pack_bf2(a.z - h2, a.w - h3));
}

__global__ void __launch_bounds__(NT, 1)
sepconv_mma_kernel(const float* __restrict__ x,
                   const float* __restrict__ dwk,    // (3,3,1,96)
                   const float* __restrict__ dwb,    // (96)
                   const float* __restrict__ pwk,    // (1,1,96,96) [ci][co]
                   const float* __restrict__ pwb,    // (96)
                   const float* __restrict__ gamma,
                   const float* __restrict__ beta,
                   const float* __restrict__ mmean,
                   const float* __restrict__ mvar,
                   float* __restrict__ out)
{
    extern __shared__ uint32_t sm[];
    uint32_t* sAhi = sm + O_AHI;
    uint32_t* sAlo = sm + O_ALO;
    uint32_t* sWhi = sm + O_WHI;
    uint32_t* sWlo = sm + O_WLO;
    float* sKw = (float*)(sm + O_KW);
    float* sSc = (float*)(sm + O_SC);
    float* sSh = (float*)(sm + O_SH);
    float* sDb = (float*)(sm + O_DB);

    const int tid = threadIdx.x;
    const int wid = tid >> 5;
    const int l   = tid & 31;
    const int w0  = blockIdx.x * TPX;
    const int h2  = blockIdx.y * 2;      // first of 2 output rows
    const int b   = blockIdx.z;

    // ---- Phase 0: stage pointwise W (bf16 hi/lo, [co][ci]), dw weights, BN --
    for (int i = tid; i < C_ * (C_ / 2); i += NT) {
        int co = i / (C_ / 2);
        int cw = i - co * (C_ / 2);          // ci word (2 channels)
        float w0f = pwk[(2 * cw) * C_ + co];
        float w1f = pwk[(2 * cw + 1) * C_ + co];
        float h0 = __bfloat162float(__float2bfloat16_rn(w0f));
        float h1 = __bfloat162float(__float2bfloat16_rn(w1f));
        sWhi[co * PW + cw] = pack_bf2(h0, h1);
        sWlo[co * PW + cw] = pack_bf2(w0f - h0, w1f - h1);
    }
    for (int i = tid; i < 9 * C_; i += NT) sKw[i] = dwk[i];
    if (tid < C_) {
        float inv = gamma[tid] * rsqrtf(mvar[tid] + 1e-3f);
        sSc[tid] = inv;
        sSh[tid] = beta[tid] - mmean[tid] * inv + pwb[tid] * inv;
        sDb[tid] = dwb[tid];
    }
    __syncthreads();

    // ---- Phase A: depthwise for 2 output rows, fixed-q per thread ----------
    // 768 items (32 groups x 24 quads), 2 per thread (stride 384 = 16*24 -> q fixed)
    {
        const float4* sKw4 = (const float4*)sKw;
        const float4* sDb4 = (const float4*)sDb;
        const int q  = tid % 24;             // FIXED channel quad
        const int g0 = tid / 24;             // 0..15

        float4 kwr[9];
        #pragma unroll
        for (int t = 0; t < 9; t++) kwr[t] = sKw4[t * 24 + q];
        const float4 dbv = sDb4[q];

        #pragma unroll
        for (int it = 0; it < 2; it++) {
            const int grp = g0 + it * 16;    // 0..31
            const int p0  = grp * 4;
            const int wwb = w0 + p0 - 1;

            float4 a00 = dbv, a01 = dbv, a02 = dbv, a03 = dbv;  // out row h2
            float4 a10 = dbv, a11 = dbv, a12 = dbv, a13 = dbv;  // out row h2+1

            #pragma unroll
            for (int rr = 0; rr < 4; rr++) {
                const int hh = h2 - 1 + rr;
                const bool hv = (unsigned)hh < (unsigned)H_;
                const float* xrow = x + ((size_t)b * H_ + hh) * (size_t)W_ * C_;

                float4 xv[6];
                #pragma unroll
                for (int cc = 0; cc < 6; cc++) {
                    const int ww = wwb + cc;
                    const bool v = hv && ((unsigned)ww < (unsigned)W_);
                    float4 t = v ? __ldg((const float4*)(xrow + (size_t)ww * C_) + q)
                                 : make_float4(0.f, 0.f, 0.f, 0.f);
                    t.x = fmaxf(t.x, 0.f); t.y = fmaxf(t.y, 0.f);
                    t.z = fmaxf(t.z, 0.f); t.w = fmaxf(t.w, 0.f);
                    xv[cc] = t;
                }
                if (rr < 3) {                       // kernel row rr for out h2
                    const float4 k0 = kwr[rr * 3 + 0];
                    const float4 k1 = kwr[rr * 3 + 1];
                    const float4 k2 = kwr[rr * 3 + 2];
                    fma4(a00, xv[0], k0); fma4(a00, xv[1], k1); fma4(a00, xv[2], k2);
                    fma4(a01, xv[1], k0); fma4(a01, xv[2], k1); fma4(a01, xv[3], k2);
                    fma4(a02, xv[2], k0); fma4(a02, xv[3], k1); fma4(a02, xv[4], k2);
                    fma4(a03, xv[3], k0); fma4(a03, xv[4], k1); fma4(a03, xv[5], k2);
                }
                if (rr >= 1) {                      // kernel row rr-1 for out h2+1
                    const float4 k0 = kwr[(rr - 1) * 3 + 0];
                    const float4 k1 = kwr[(rr - 1) * 3 + 1];
                    const float4 k2 = kwr[(rr - 1) * 3 + 2];
                    fma4(a10, xv[0], k0); fma4(a10, xv[1], k1); fma4(a10, xv[2], k2);
                    fma4(a11, xv[1], k0); fma4(a11, xv[2], k1); fma4(a11, xv[3], k2);
                    fma4(a12, xv[2], k0); fma4(a12, xv[3], k1); fma4(a12, xv[4], k2);
                    fma4(a13, xv[3], k0); fma4(a13, xv[4], k1); fma4(a13, xv[5], k2);
                }
            }

            store_split(sAhi, sAlo, p0 + 0, q, a00);
            store_split(sAhi, sAlo, p0 + 1, q, a01);
            store_split(sAhi, sAlo, p0 + 2, q, a02);
            store_split(sAhi, sAlo, p0 + 3, q, a03);
            store_split(sAhi, sAlo, 128 + p0 + 0, q, a10);
            store_split(sAhi, sAlo, 128 + p0 + 1, q, a11);
            store_split(sAhi, sAlo, 128 + p0 + 2, q, a12);
            store_split(sAhi, sAlo, 128 + p0 + 3, q, a13);
        }
    }
    __syncthreads();

    // ---- Phase B: GEMM M=256 N=96 K=96; 12 warps = 4M x 3N -----------------
    // warp = 64 M-rows (4 mtiles) x 32 N-cols (2 j-pairs); d = 64 regs
    const int wid_m = wid / 3;           // 0..3
    const int wid_n = wid - wid_m * 3;   // 0..2
    const int m0  = wid_m * 64;
    const int n0  = wid_n * 32;
    const int jpb = wid_n * 2;           // global j-pair base
    const int g   = l >> 2;
    const int tg  = l & 3;

    const uint32_t sbase = smem_u32(sm);
    const int arowl = ((l >> 3) & 1) * 8 + (l & 7);
    const int acol  = (l >> 4) * 4;
    const int browl = ((l >> 4) * 8) + (l & 7);
    const int bcol  = ((l >> 3) & 1) * 4;

    const uint32_t a_hi = sbase + (uint32_t)(O_AHI + (m0 + arowl) * PW + acol) * 4u;
    const uint32_t a_lo = sbase + (uint32_t)(O_ALO + (m0 + arowl) * PW + acol) * 4u;
    const uint32_t b_hi = sbase + (uint32_t)(O_WHI + (jpb * 16 + browl) * PW + bcol) * 4u;
    const uint32_t b_lo = sbase + (uint32_t)(O_WLO + (jpb * 16 + browl) * PW + bcol) * 4u;

    float d[4][2][2][4];                 // [mt][jj][j8-in-pair][4]
    #pragma unroll
    for (int mt = 0; mt < 4; mt++)
        #pragma unroll
        for (int jj = 0; jj < 2; jj++)
            #pragma unroll
            for (int jl = 0; jl < 2; jl++) {
                d[mt][jj][jl][0] = 0.f; d[mt][jj][jl][1] = 0.f;
                d[mt][jj][jl][2] = 0.f; d[mt][jj][jl][3] = 0.f;
            }

    #pragma unroll
    for (int k = 0; k < 6; k++) {
        uint32_t ah[4][4], al[4][4];
        #pragma unroll
        for (int mt = 0; mt < 4; mt++) {
            const uint32_t moff = (uint32_t)mt * (16u * PW * 4u) + k * 32u;
            ldsm_x4(ah[mt], a_hi + moff);
            ldsm_x4(al[mt], a_lo + moff);
        }
        #pragma unroll
        for (int jj = 0; jj < 2; jj++) {
            uint32_t bh[4], bl[4];
            const uint32_t joff = (uint32_t)jj * (16u * PW * 4u) + k * 32u;
            ldsm_x4(bh, b_hi + joff);
            ldsm_x4(bl, b_lo + joff);
            #pragma unroll
            for (int mt = 0; mt < 4; mt++) {
                float* d0 = d[mt][jj][0];
                float* d1 = d[mt][jj][1];
                mma16816(d0, ah[mt][0], ah[mt][1], ah[mt][2], ah[mt][3], bh[0], bh[1]);
                mma16816(d0, ah[mt][0], ah[mt][1], ah[mt][2], ah[mt][3], bl[0], bl[1]);
                mma16816(d0, al[mt][0], al[mt][1], al[mt][2], al[mt][3], bh[0], bh[1]);
                mma16816(d1, ah[mt][0], ah[mt][1], ah[mt][2], ah[mt][3], bh[2], bh[3]);
                mma16816(d1, ah[mt][0], ah[mt][1], ah[mt][2], ah[mt][3], bl[2], bl[3]);
                mma16816(d1, al[mt][0], al[mt][1], al[mt][2], al[mt][3], bh[2], bh[3]);
            }
        }
    }

    // ---- Epilogue: BN + store ---------------------------------------------
    #pragma unroll
    for (int mt = 0; mt < 4; mt++) {
        #pragma unroll
        for (int jj = 0; jj < 2; jj++) {
            #pragma unroll
            for (int jl = 0; jl < 2; jl++) {
                const int col = n0 + (jj * 2 + jl) * 8 + tg * 2;
                const float2 sc = *(const float2*)(sSc + col);
                const float2 sh = *(const float2*)(sSh + col);
                const float* dd = d[mt][jj][jl];
                #pragma unroll
                for (int half = 0; half < 2; half++) {
                    const int row = m0 + mt * 16 + g + half * 8;
                    const int px  = row & 127;
                    const int orow = h2 + (row >> 7);
                    if (px < TPX) {
                        float2 r;
                        r.x = fmaf(dd[half * 2 + 0], sc.x, sh.x);
                        r.y = fmaf(dd[half * 2 + 1], sc.y, sh.y);
                        *(float2*)(out + (((size_t)b * H_ + orow) * W_ + (w0 + px)) * C_ + col) = r;
                    }
                }
            }
        }
    }
}

extern "C" void kernel_launch(void* const* d_in, const int* in_sizes, int n_in,
                              void* d_out, int out_size)
{
    (void)in_sizes; (void)n_in; (void)out_size;
    const float* x     = (const float*)d_in[0];
    const float* dwk   = (const float*)d_in[1];
    const float* dwb   = (const float*)d_in[2];
    const float* pwk   = (const float*)d_in[3];
    const float* pwb   = (const float*)d_in[4];
    const float* gamma = (const float*)d_in[5];
    const float* beta  = (const float*)d_in[6];
    const float* mmean = (const float*)d_in[7];
    const float* mvar  = (const float*)d_in[8];
    float* out = (float*)d_out;

    cudaFuncSetAttribute(sepconv_mma_kernel,
                         cudaFuncAttributeMaxDynamicSharedMemorySize, SMEM_BYTES);

    dim3 grid(W_ / TPX, H_ / 2, B_);       // (2, 112, 16)
    sepconv_mma_kernel<<<grid, NT, SMEM_BYTES>>>(
        x, dwk, dwb, pwk, pwb, gamma, beta, mmean, mvar, out);
}

// round 17
// speedup vs baseline: 2.3710x; 1.2408x over previous
#include <cuda_runtime.h>
#include <cuda_bf16.h>
#include <cstdint>

// ---------------- problem constants ----------------
#define B_   16
#define H_   224
#define W_   224
#define C_   96
#define TPX  112          // valid pixels per block (per output row)
#define NT   384          // 12 warps
#define PW   52           // smem row pitch in 32-bit words (=104 bf16)

// ---------------- smem layout (uint32 words) ----------------
// A: 256 rows (row p = out-row h2 pixel p; row 128+p = out-row h2+1)
// The sAhi region doubles as the pwk staging scratch before Phase A.
#define O_AHI 0                          // 256*52 = 13312
#define O_ALO 13312
#define O_WHI 26624                      // W hi: 96 x 52
#define O_WLO 31616
#define O_KW  36608                      // dw weights 9*96 f32
#define O_SC  (O_KW + 9 * 96)
#define O_SH  (O_SC + 96)
#define O_DB  (O_SH + 96)
#define SMEM_WORDS (O_DB + 96)           // 37760
#define SMEM_BYTES (SMEM_WORDS * 4)      // 151040

__device__ __forceinline__ void mma16816(float* d,
    uint32_t a0, uint32_t a1, uint32_t a2, uint32_t a3,
    uint32_t b0, uint32_t b1)
{
    asm volatile(
        "mma.sync.aligned.m16n8k16.row.col.f32.bf16.bf16.f32 "
        "{%0,%1,%2,%3}, {%4,%5,%6,%7}, {%8,%9}, {%0,%1,%2,%3};"
        : "+f"(d[0]), "+f"(d[1]), "+f"(d[2]), "+f"(d[3])
        : "r"(a0), "r"(a1), "r"(a2), "r"(a3), "r"(b0), "r"(b1));
}

__device__ __forceinline__ void ldsm_x4(uint32_t* r, uint32_t addr) {
    asm volatile(
        "ldmatrix.sync.aligned.m8n8.x4.shared.b16 {%0,%1,%2,%3}, [%4];"
        : "=r"(r[0]), "=r"(r[1]), "=r"(r[2]), "=r"(r[3]) : "r"(addr));
}

__device__ __forceinline__ uint32_t smem_u32(const void* p) {
    uint32_t a;
    asm("{ .reg .u64 t; cvta.to.shared.u64 t, %1; cvt.u32.u64 %0, t; }"
        : "=r"(a) : "l"(p));
    return a;
}

__device__ __forceinline__ uint32_t pack_bf2(float lo, float hi) {
    __nv_bfloat162 v = __floats2bfloat162_rn(lo, hi);   // .x = lo lane
    return *(uint32_t*)&v;
}

__device__ __forceinline__ void fma4(float4& a, const float4& xv, const float4& k) {
    a.x = fmaf(xv.x, k.x, a.x);
    a.y = fmaf(xv.y, k.y, a.y);
    a.z = fmaf(xv.z, k.z, a.z);
    a.w = fmaf(xv.w, k.w, a.w);
}

__device__ __forceinline__ void store_split(uint32_t* sAhi, uint32_t* sAlo,
                                            int row, int q, float4 a)
{
    float h0 = __bfloat162float(__float2bfloat16_rn(a.x));
    float h1 = __bfloat162float(__float2bfloat16_rn(a.y));
    float h2 = __bfloat162float(__float2bfloat16_rn(a.z));
    float h3 = __bfloat162float(__float2bfloat16_rn(a.w));
    const int wb = row * PW + q * 2;
    *(uint2*)(sAhi + wb) = make_uint2(pack_bf2(h0, h1), pack_bf2(h2, h3));
    *(uint2*)(sAlo + wb) = make_uint2(pack_bf2(a.x - h0, a.y - h1),
                                      pack_bf2(a.z - h2, a.w - h3));
}

__global__ void __launch_bounds__(NT, 1)
sepconv_mma_kernel(const float* __restrict__ x,
                   const float* __restrict__ dwk,    // (3,3,1,96)
                   const float* __restrict__ dwb,    // (96)
                   const float* __restrict__ pwk,    // (1,1,96,96) [ci][co]
                   const float* __restrict__ pwb,    // (96)
                   const float* __restrict__ gamma,
                   const float* __restrict__ beta,
                   const float* __restrict__ mmean,
                   const float* __restrict__ mvar,
                   float* __restrict__ out)
{
    extern __shared__ uint32_t sm[];
    uint32_t* sAhi = sm + O_AHI;
    uint32_t* sAlo = sm + O_ALO;
    float* sScr = (float*)(sm + O_AHI);              // pwk staging scratch
    __nv_bfloat16* sWhiH = (__nv_bfloat16*)(sm + O_WHI);
    __nv_bfloat16* sWloH = (__nv_bfloat16*)(sm + O_WLO);
    float* sKw = (float*)(sm + O_KW);
    float* sSc = (float*)(sm + O_SC);
    float* sSh = (float*)(sm + O_SH);
    float* sDb = (float*)(sm + O_DB);

    const int tid = threadIdx.x;
    const int wid = tid >> 5;
    const int l   = tid & 31;
    const int w0  = blockIdx.x * TPX;
    const int h2  = blockIdx.y * 2;      // first of 2 output rows
    const int b   = blockIdx.z;

    // ---- Phase -1: COALESCED pwk read into scratch; dw weights; BN ---------
    {
        const float4* src = (const float4*)pwk;      // 2304 float4, linear
        float4* dst = (float4*)sScr;
        #pragma unroll
        for (int i = tid; i < (C_ * C_) / 4; i += NT) dst[i] = src[i];
    }
    for (int i = tid; i < 9 * C_; i += NT) sKw[i] = dwk[i];
    if (tid < C_) {
        float inv = gamma[tid] * rsqrtf(mvar[tid] + 1e-3f);
        sSc[tid] = inv;
        sSh[tid] = beta[tid] - mmean[tid] * inv + pwb[tid] * inv;
        sDb[tid] = dwb[tid];
    }
    __syncthreads();

    // ---- Phase 0: smem transpose -> bf16 hi/lo W[co][ci] (104-half pitch) --
    #pragma unroll
    for (int i = tid; i < C_ * C_; i += NT) {
        const int ci = i / C_;           // lanes sweep co -> LDS conflict-free
        const int co = i - ci * C_;
        const float wv = sScr[ci * C_ + co];
        const __nv_bfloat16 hb = __float2bfloat16_rn(wv);
        const __nv_bfloat16 lb = __float2bfloat16_rn(wv - __bfloat162float(hb));
        sWhiH[co * (2 * PW) + ci] = hb;
        sWloH[co * (2 * PW) + ci] = lb;
    }
    __syncthreads();

    // ---- Phase A: depthwise, 8-pixel items, one per thread -----------------
    // 384 threads = 16 groups x 24 quads; group owns 8 pixels, q fixed.
    {
        const float4* sKw4 = (const float4*)sKw;
        const float4* sDb4 = (const float4*)sDb;
        const int q   = tid % 24;            // FIXED channel quad
        const int grp = tid / 24;            // 0..15
        const int p0  = grp * 8;
        const int wwb = w0 + p0 - 1;

        const float4 dbv = sDb4[q];
        float4 a0[8], a1[8];
        #pragma unroll
        for (int e = 0; e < 8; e++) { a0[e] = dbv; a1[e] = dbv; }

        float4 kprev[3];
        #pragma unroll
        for (int rr = 0; rr < 4; rr++) {
            const int hh = h2 - 1 + rr;
            const bool hv = (unsigned)hh < (unsigned)H_;
            const float* xrow = x + ((size_t)b * H_ + hh) * (size_t)W_ * C_;

            float4 kcur[3];
            if (rr < 3) {
                #pragma unroll
                for (int s = 0; s < 3; s++) kcur[s] = sKw4[(rr * 3 + s) * 24 + q];
            }

            float4 xv[10];
            #pragma unroll
            for (int cc = 0; cc < 10; cc++) {
                const int ww = wwb + cc;
                const bool v = hv && ((unsigned)ww < (unsigned)W_);
                float4 t = v ? __ldg((const float4*)(xrow + (size_t)ww * C_) + q)
                             : make_float4(0.f, 0.f, 0.f, 0.f);
                t.x = fmaxf(t.x, 0.f); t.y = fmaxf(t.y, 0.f);
                t.z = fmaxf(t.z, 0.f); t.w = fmaxf(t.w, 0.f);
                xv[cc] = t;
            }
            if (rr < 3) {
                #pragma unroll
                for (int e = 0; e < 8; e++) {
                    fma4(a0[e], xv[e + 0], kcur[0]);
                    fma4(a0[e], xv[e + 1], kcur[1]);
                    fma4(a0[e], xv[e + 2], kcur[2]);
                }
            }
            if (rr >= 1) {
                #pragma unroll
                for (int e = 0; e < 8; e++) {
                    fma4(a1[e], xv[e + 0], kprev[0]);
                    fma4(a1[e], xv[e + 1], kprev[1]);
                    fma4(a1[e], xv[e + 2], kprev[2]);
                }
            }
            #pragma unroll
            for (int s = 0; s < 3; s++) kprev[s] = kcur[s];
        }

        #pragma unroll
        for (int e = 0; e < 8; e++) {
            store_split(sAhi, sAlo, p0 + e, q, a0[e]);
            store_split(sAhi, sAlo, 128 + p0 + e, q, a1[e]);
        }
    }
    __syncthreads();

    // ---- Phase B: GEMM M=256 N=96 K=96; 12 warps = 4M x 3N -----------------
    const int wid_m = wid / 3;           // 0..3
    const int wid_n = wid - wid_m * 3;   // 0..2
    const int m0  = wid_m * 64;
    const int n0  = wid_n * 32;
    const int jpb = wid_n * 2;           // global j-pair base
    const int g   = l >> 2;
    const int tg  = l & 3;

    const uint32_t sbase = smem_u32(sm);
    const int arowl = ((l >> 3) & 1) * 8 + (l & 7);
    const int acol  = (l >> 4) * 4;
    const int browl = ((l >> 4) * 8) + (l & 7);
    const int bcol  = ((l >> 3) & 1) * 4;

    const uint32_t a_hi = sbase + (uint32_t)(O_AHI + (m0 + arowl) * PW + acol) * 4u;
    const uint32_t a_lo = sbase + (uint32_t)(O_ALO + (m0 + arowl) * PW + acol) * 4u;
    const uint32_t b_hi = sbase + (uint32_t)(O_WHI + (jpb * 16 + browl) * PW + bcol) * 4u;
    const uint32_t b_lo = sbase + (uint32_t)(O_WLO + (jpb * 16 + browl) * PW + bcol) * 4u;

    float d[4][2][2][4];                 // [mt][jj][j8-in-pair][4]
    #pragma unroll
    for (int mt = 0; mt < 4; mt++)
        #pragma unroll
        for (int jj = 0; jj < 2; jj++)
            #pragma unroll
            for (int jl = 0; jl < 2; jl++) {
                d[mt][jj][jl][0] = 0.f; d[mt][jj][jl][1] = 0.f;
                d[mt][jj][jl][2] = 0.f; d[mt][jj][jl][3] = 0.f;
            }

    #pragma unroll
    for (int k = 0; k < 6; k++) {
        uint32_t ah[4][4], al[4][4];
        #pragma unroll
        for (int mt = 0; mt < 4; mt++) {
            const uint32_t moff = (uint32_t)mt * (16u * PW * 4u) + k * 32u;
            ldsm_x4(ah[mt], a_hi + moff);
            ldsm_x4(al[mt], a_lo + moff);
        }
        #pragma unroll
        for (int jj = 0; jj < 2; jj++) {
            uint32_t bh[4], bl[4];
            const uint32_t joff = (uint32_t)jj * (16u * PW * 4u) + k * 32u;
            ldsm_x4(bh, b_hi + joff);
            ldsm_x4(bl, b_lo + joff);
            #pragma unroll
            for (int mt = 0; mt < 4; mt++) {
                float* d0 = d[mt][jj][0];
                float* d1 = d[mt][jj][1];
                mma16816(d0, ah[mt][0], ah[mt][1], ah[mt][2], ah[mt][3], bh[0], bh[1]);
                mma16816(d0, ah[mt][0], ah[mt][1], ah[mt][2], ah[mt][3], bl[0], bl[1]);
                mma16816(d0, al[mt][0], al[mt][1], al[mt][2], al[mt][3], bh[0], bh[1]);
                mma16816(d1, ah[mt][0], ah[mt][1], ah[mt][2], ah[mt][3], bh[2], bh[3]);
                mma16816(d1, ah[mt][0], ah[mt][1], ah[mt][2], ah[mt][3], bl[2], bl[3]);
                mma16816(d1, al[mt][0], al[mt][1], al[mt][2], al[mt][3], bh[2], bh[3]);
            }
        }
    }

    // ---- Epilogue: BN + store ---------------------------------------------
    #pragma unroll
    for (int mt = 0; mt < 4; mt++) {
        #pragma unroll
        for (int jj = 0; jj < 2; jj++) {
            #pragma unroll
            for (int jl = 0; jl < 2; jl++) {
                const int col = n0 + (jj * 2 + jl) * 8 + tg * 2;
                const float2 sc = *(const float2*)(sSc + col);
                const float2 sh = *(const float2*)(sSh + col);
                const float* dd = d[mt][jj][jl];
                #pragma unroll
                for (int half = 0; half < 2; half++) {
                    const int row = m0 + mt * 16 + g + half * 8;
                    const int px  = row & 127;
                    const int orow = h2 + (row >> 7);
                    if (px < TPX) {
                        float2 r;
                        r.x = fmaf(dd[half * 2 + 0], sc.x, sh.x);
                        r.y = fmaf(dd[half * 2 + 1], sc.y, sh.y);
                        *(float2*)(out + (((size_t)b * H_ + orow) * W_ + (w0 + px)) * C_ + col) = r;
                    }
                }
            }
        }
    }
}

extern "C" void kernel_launch(void* const* d_in, const int* in_sizes, int n_in,
                              void* d_out, int out_size)
{
    (void)in_sizes; (void)n_in; (void)out_size;
    const float* x     = (const float*)d_in[0];
    const float* dwk   = (const float*)d_in[1];
    const float* dwb   = (const float*)d_in[2];
    const float* pwk   = (const float*)d_in[3];
    const float* pwb   = (const float*)d_in[4];
    const float* gamma = (const float*)d_in[5];
    const float* beta  = (const float*)d_in[6];
    const float* mmean = (const float*)d_in[7];
    const float* mvar  = (const float*)d_in[8];
    float* out = (float*)d_out;

    cudaFuncSetAttribute(sepconv_mma_kernel,
                         cudaFuncAttributeMaxDynamicSharedMemorySize, SMEM_BYTES);

    dim3 grid(W_ / TPX, H_ / 2, B_);       // (2, 112, 16)
    sepconv_mma_kernel<<<grid, NT, SMEM_BYTES>>>(
        x, dwk, dwb, pwk, pwb, gamma, beta, mmean, mvar, out);
}